// round 16
// baseline (speedup 1.0000x reference)
#include <cuda_runtime.h>
#include <cuda_bf16.h>
#include <cuda_fp16.h>
#include <math.h>
#include <stdint.h>

// Problem constants
#define BB    32
#define SS    512
#define HH    768
#define NHH   12
#define HDD   64
#define NCOLL 32
#define MM    (BB*SS)     // 16384 rows
#define NQKV  (3*HH)      // 2304

#if defined(__CUDA_ARCH__) && (defined(__CUDA_ARCH_FEAT_SM103_ALL) || defined(__CUDA_ARCH_FEAT_SM100_ALL) || defined(__CUDA_ARCH_SPECIFIC__))
#define HAS_TCGEN05 1
#else
#define HAS_TCGEN05 0
#endif

// ---------------- helpers ----------------------------------------------------
__device__ __forceinline__ uint32_t smem_u32(const void* p) {
    uint32_t a;
    asm("{ .reg .u64 t; cvta.to.shared.u64 t, %1; cvt.u32.u64 %0, t; }" : "=r"(a) : "l"(p));
    return a;
}
#define SMEM_SWIZZLE_128B(o) ((o) ^ (((o) >> 3) & 0x70))

// chunked+pre-swizzled gmem layout for bf16 GEMM operands:
// element (r,k) of an [R rows, K cols] array lives at
//   ((k>>6)*R + r)*64 + ((k&63) ^ ((r&7)<<3))          [element units]
// so every (K-64-chunk x 128-row) slice is a contiguous 16KB block whose bytes
// are already in tcgen05 SW128 smem order -> ONE bulk TMA copy per chunk.
__device__ __host__ __forceinline__ size_t chunk_off(size_t R, int r, int k) {
    return ((size_t)((unsigned)k >> 6) * R + (size_t)r) * 64
         + (size_t)((((unsigned)k) & 63u) ^ ((((unsigned)r) & 7u) << 3));
}

__device__ __forceinline__ uint32_t pack_bf2(__nv_bfloat16 a, __nv_bfloat16 b) {
    __nv_bfloat162 t; t.x = a; t.y = b;
    return *reinterpret_cast<uint32_t*>(&t);
}
__device__ __forceinline__ void split_one(float x, __nv_bfloat16& hi, __nv_bfloat16& lo) {
    __nv_bfloat16 h = __float2bfloat16(x);
    hi = h;
    lo = __float2bfloat16(x - __bfloat162float(h));
}
__device__ __forceinline__ float gelu_f(float x) {
    return 0.5f * x * (1.f + erff(x * 0.70710678118654752f));
}

#if HAS_TCGEN05
__device__ __forceinline__ uint32_t elect_one_pred() {
    uint32_t pred;
    asm volatile("{\n\t.reg .pred p;\n\telect.sync _|p, 0xFFFFFFFF;\n\tselp.b32 %0, 1, 0, p;\n\t}" : "=r"(pred));
    return pred;
}

static constexpr uint64_t SMEM_DESC_BASE_SW128 =
    (uint64_t(2) << 61) | (uint64_t(1) << 46) | (uint64_t(64) << 32) | (uint64_t(1) << 16);
#define MAKE_SMEM_DESC(base_addr) \
    (SMEM_DESC_BASE_SW128 | ((uint64_t)((base_addr) >> 4) & 0x3FFF))

#define FENCE_PROXY_ASYNC() \
    asm volatile("fence.proxy.async.shared::cta;" ::: "memory")

// bulk async copy 16KB-class block, completion via mbarrier complete_tx
#define CP_BULK(dst_u32, src_ptr, bytes, mbar) \
    asm volatile("cp.async.bulk.shared::cluster.global.mbarrier::complete_tx::bytes [%0], [%1], %2, [%3];" \
        :: "r"((uint32_t)(dst_u32)), "l"(src_ptr), "r"((uint32_t)(bytes)), "r"((uint32_t)(mbar)) : "memory")
#define MBARRIER_EXPECT_TX(mbar, tx) \
    asm volatile("mbarrier.arrive.expect_tx.shared.b64 _, [%0], %1;" \
        :: "r"((uint32_t)(mbar)), "r"((uint32_t)(tx)) : "memory")

#define TCGEN05_ALLOC(smem_result_addr, nCols) \
    asm volatile("tcgen05.alloc.cta_group::1.sync.aligned.shared::cta.b32 [%0], %1;" \
        :: "r"((uint32_t)(smem_result_addr)), "r"((uint32_t)(nCols)) : "memory")
#define TCGEN05_DEALLOC(tmem_addr, nCols) \
    asm volatile("tcgen05.dealloc.cta_group::1.sync.aligned.b32 %0, %1;" :: "r"(tmem_addr), "r"((uint32_t)(nCols)))
#define TCGEN05_RELINQ() \
    asm volatile("tcgen05.relinquish_alloc_permit.cta_group::1.sync.aligned;")
#define TCGEN05_COMMIT(mbar) \
    asm volatile("tcgen05.commit.cta_group::1.mbarrier::arrive::one.shared::cluster.b64 [%0];" \
        :: "r"((uint32_t)(mbar)) : "memory")
#define TCGEN05_FENCE_AFTER()  asm volatile("tcgen05.fence::after_thread_sync;" ::: "memory")
#define TCGEN05_FENCE_BEFORE() asm volatile("tcgen05.fence::before_thread_sync;" ::: "memory")
#define TCGEN05_WAIT_LD() asm volatile("tcgen05.wait::ld.sync.aligned;" ::: "memory")

#define MBARRIER_INIT(mbar, count) \
    asm volatile("mbarrier.init.shared.b64 [%0], %1;" :: "r"((uint32_t)(mbar)), "r"((uint32_t)(count)) : "memory")
#define MBARRIER_INVAL(mbar) \
    asm volatile("mbarrier.inval.shared.b64 [%0];" :: "r"((uint32_t)(mbar)) : "memory")
#define MBARRIER_WAIT_PARITY(mbar_smem_addr, phase_parity) do { \
    uint32_t _mbar = (uint32_t)(mbar_smem_addr); \
    uint32_t _parity = (uint32_t)(phase_parity); \
    uint32_t _done; \
    asm volatile("{\n\t.reg .pred p;\n\t" \
        "mbarrier.try_wait.parity.acquire.cta.shared::cta.b64 p, [%1], %2;\n\t" \
        "selp.b32 %0, 1, 0, p;\n\t}" : "=r"(_done) : "r"(_mbar), "r"(_parity) : "memory"); \
    if (!_done) { \
        asm volatile("{\n\t.reg .pred P1;\n\t" \
            "WAIT_LOOP_%=:\n\t" \
            "mbarrier.try_wait.parity.acquire.cta.shared::cta.b64 P1, [%0], %1, 0x989680;\n\t" \
            "@P1 bra.uni WAIT_DONE_%=;\n\t" \
            "bra.uni WAIT_LOOP_%=;\n\t" \
            "WAIT_DONE_%=:\n\t}" :: "r"(_mbar), "r"(_parity) : "memory"); \
    } \
} while(0)

#define TCGEN05_LD_32X32B_X32(r, tmem_addr) \
    asm volatile("tcgen05.ld.sync.aligned.32x32b.x32.b32 " \
        "{%0, %1, %2, %3, %4, %5, %6, %7, %8, %9, %10, %11, %12, %13, %14, %15, " \
        " %16, %17, %18, %19, %20, %21, %22, %23, %24, %25, %26, %27, %28, %29, %30, %31}, [%32];" \
        : "=r"((r)[0]),  "=r"((r)[1]),  "=r"((r)[2]),  "=r"((r)[3]), \
          "=r"((r)[4]),  "=r"((r)[5]),  "=r"((r)[6]),  "=r"((r)[7]), \
          "=r"((r)[8]),  "=r"((r)[9]),  "=r"((r)[10]), "=r"((r)[11]), \
          "=r"((r)[12]), "=r"((r)[13]), "=r"((r)[14]), "=r"((r)[15]), \
          "=r"((r)[16]), "=r"((r)[17]), "=r"((r)[18]), "=r"((r)[19]), \
          "=r"((r)[20]), "=r"((r)[21]), "=r"((r)[22]), "=r"((r)[23]), \
          "=r"((r)[24]), "=r"((r)[25]), "=r"((r)[26]), "=r"((r)[27]), \
          "=r"((r)[28]), "=r"((r)[29]), "=r"((r)[30]), "=r"((r)[31]) \
        : "r"(tmem_addr))

#define TCGEN05_LD_32X32B_X16(r, tmem_addr) \
    asm volatile("tcgen05.ld.sync.aligned.32x32b.x16.b32 " \
        "{%0, %1, %2, %3, %4, %5, %6, %7, %8, %9, %10, %11, %12, %13, %14, %15}, [%16];" \
        : "=r"((r)[0]),  "=r"((r)[1]),  "=r"((r)[2]),  "=r"((r)[3]), \
          "=r"((r)[4]),  "=r"((r)[5]),  "=r"((r)[6]),  "=r"((r)[7]), \
          "=r"((r)[8]),  "=r"((r)[9]),  "=r"((r)[10]), "=r"((r)[11]), \
          "=r"((r)[12]), "=r"((r)[13]), "=r"((r)[14]), "=r"((r)[15]) \
        : "r"(tmem_addr))

__device__ __forceinline__ void mma_f16_ss(uint32_t d_tmem, uint64_t a_desc, uint64_t b_desc,
                                           uint32_t idesc, int enable_d) {
    asm volatile(
        "{\n\t.reg .pred p;\n\t"
        "setp.ne.u32 p, %5, 0;\n\t"
        "tcgen05.mma.cta_group::1.kind::f16 [%0], %1, %2, %3, {%4, %4, %4, %4}, p;\n\t}"
        :: "r"(d_tmem), "l"(a_desc), "l"(b_desc), "r"(idesc), "r"(0u), "r"((uint32_t)enable_d)
        : "memory");
}

// idesc: dtype F32, a/b BF16, M=128, N=128
#define GEMM_IDESC_N128 ((1u<<4) | (1u<<7) | (1u<<10) | ((128u/8u)<<17) | ((128u/16u)<<24))
// idesc: dtype F32, a/b F16, N=64, M=128 (K-major both sides)
#define PV_IDESC   ((1u<<4) | ((64u/8u)<<17) | ((128u/16u)<<24))

__device__ __forceinline__ uint32_t exp2_f16x2(float lo, float hi) {
    uint32_t p, r;
    asm("cvt.rn.f16x2.f32 %0, %1, %2;" : "=r"(p) : "f"(hi), "f"(lo));
    asm("ex2.approx.f16x2 %0, %1;" : "=r"(r) : "r"(p));
    return r;
}
#endif // HAS_TCGEN05

// ---------------- scratch (chunked bf16 arrays 128B-aligned for bulk TMA) -----
__device__ __align__(128) __nv_bfloat16 g_hid_hi[(size_t)MM*HH];
__device__ __align__(128) __nv_bfloat16 g_hid_lo[(size_t)MM*HH];
__device__ __align__(128) __nv_bfloat16 g_Wd_hi[(size_t)HH*HH];
__device__ __align__(128) __nv_bfloat16 g_Wd_lo[(size_t)HH*HH];
__device__ __align__(128) __nv_bfloat16 g_Wc_hi[(size_t)HH*HH];
__device__ __align__(128) __nv_bfloat16 g_Wc_lo[(size_t)HH*HH];
__device__ __align__(128) __nv_bfloat16 g_ce_hi[(size_t)BB*NCOLL*HH];
__device__ __align__(128) __nv_bfloat16 g_ce_lo[(size_t)BB*NCOLL*HH];
__device__ float         g_colproj[(size_t)BB*NCOLL*HH];
__device__ int           g_rowsrc[MM];
__device__ float         g_bcat[HH];
__device__ float         g_zero[HH];
__device__ __align__(128) __nv_bfloat16 g_Wqkv_hi[(size_t)NQKV*HH];
__device__ __align__(128) __nv_bfloat16 g_Wqkv_lo[(size_t)NQKV*HH];
__device__ float         g_bqkv[NQKV];
__device__ __align__(128) __nv_bfloat16 g_Wo_hi[(size_t)HH*HH];
__device__ __align__(128) __nv_bfloat16 g_Wo_lo[(size_t)HH*HH];
__device__ float         g_h[(size_t)MM*HH];
__device__ __align__(128) __nv_bfloat16 g_h_hi[(size_t)MM*HH];
__device__ __align__(128) __nv_bfloat16 g_h_lo[(size_t)MM*HH];
__device__ float         g_qkv[(size_t)MM*NQKV];
__device__ __align__(128) __nv_bfloat16 g_ctx_hi[(size_t)MM*HH];
__device__ __align__(128) __nv_bfloat16 g_ctx_lo[(size_t)MM*HH];
__device__ float         g_proj[(size_t)MM*HH];

// ---------------- merged prep (writes chunked layout) -------------------------
__global__ void prep_all(const float* __restrict__ Wd, const float* __restrict__ bd,
                         const float* __restrict__ Wc, const float* __restrict__ bc,
                         const float* __restrict__ Wq, const float* __restrict__ bq,
                         const float* __restrict__ Wk, const float* __restrict__ bk,
                         const float* __restrict__ Wv, const float* __restrict__ bv,
                         const float* __restrict__ Wo,
                         const float* __restrict__ colemb,
                         const int* __restrict__ cat, const int* __restrict__ vmask) {
    int i = blockIdx.x * blockDim.x + threadIdx.x;
    if (i < NQKV * HH) {
        int n = i / HH, k = i % HH;
        float v;
        if (n < HH)        v = Wq[n*HH + k];
        else if (n < 2*HH) v = Wk[(n-HH)*HH + k];
        else               v = Wv[(n-2*HH)*HH + k];
        size_t o = chunk_off(NQKV, n, k);
        split_one(v, g_Wqkv_hi[o], g_Wqkv_lo[o]);
    }
    if (i < HH*HH) {
        int n = i / HH, k = i % HH;
        size_t o = chunk_off(HH, n, k);
        split_one(Wd[i], g_Wd_hi[o], g_Wd_lo[o]);
        split_one(Wc[i], g_Wc_hi[o], g_Wc_lo[o]);
        split_one(Wo[i], g_Wo_hi[o], g_Wo_lo[o]);
    }
    if (i < BB*NCOLL*HH) {
        int bc_ = i / HH, k = i % HH;
        float v = (cat[bc_] == 1) ? colemb[i] : 0.f;
        size_t o = chunk_off(BB*NCOLL, bc_, k);
        split_one(v, g_ce_hi[o], g_ce_lo[o]);
    }
    if (i < MM) {
        int b = i / SS;
        int idx = vmask[i];
        int rs = -1;
        if (idx > 0 && cat[b*NCOLL + idx - 1] == 1) rs = b*NCOLL + idx - 1;
        g_rowsrc[i] = rs;
    }
    if (i < NQKV) {
        float v;
        if (i < HH)        v = bq[i];
        else if (i < 2*HH) v = bk[i-HH];
        else               v = bv[i-2*HH];
        g_bqkv[i] = v;
    }
    if (i < HH) g_bcat[i] = bd[i] + bc[i];
}

__global__ void split_f32_ch(const float* __restrict__ x, __nv_bfloat16* __restrict__ hi,
                             __nv_bfloat16* __restrict__ lo, int R, int K) {
    int i = blockIdx.x * blockDim.x + threadIdx.x;
    if (i < R * K) {
        int r = i / K, k = i % K;
        size_t o = chunk_off((size_t)R, r, k);
        split_one(x[i], hi[o], lo[o]);
    }
}

// ---------------- tcgen05 bf16x3-split GEMM, bulk-TMA 3-stage pipeline --------
// 128x128 tile; chunk = K-64 slice; stage = Ahi|Alo|Bhi|Blo (64KB, one 16KB
// bulk TMA per array). 12 MMA dispatches per chunk. tid0 drives the whole
// pipeline; all 128 threads do the epilogue. 3 stages = 193KB -> 1 CTA/SM.
#define GSTAGE 65536
#define GEMM_SMEM_BYTES (1024 + 3*GSTAGE)

__global__ __launch_bounds__(128, 1)
void gemm_bf16x3(const __nv_bfloat16* __restrict__ Ahi, const __nv_bfloat16* __restrict__ Alo,
                 const __nv_bfloat16* __restrict__ Bhi, const __nv_bfloat16* __restrict__ Blo,
                 const float* __restrict__ bias, float* __restrict__ C,
                 __nv_bfloat16* __restrict__ Chi, __nv_bfloat16* __restrict__ Clo,
                 int Md, int Nd, int Kd, int gelu_act,
                 const float* __restrict__ addsrc, const int* __restrict__ rowsrc) {
#if HAS_TCGEN05
    extern __shared__ __align__(1024) char smem[];
    const uint32_t sbase = smem_u32(smem);
    const int tid = threadIdx.x;
    const int wid = tid >> 5;
    const int m0 = blockIdx.y * 128;
    const int n0 = blockIdx.x * 128;

    if (wid == 0) { TCGEN05_ALLOC(sbase, 128); TCGEN05_RELINQ(); }
    if (tid == 0) {
#pragma unroll
        for (int s = 0; s < 3; s++) {
            MBARRIER_INIT(sbase + 8  + s * 8, 1);    // full[s]  (complete_tx)
            MBARRIER_INIT(sbase + 32 + s * 8, 1);    // empty[s] (MMA commit)
        }
        MBARRIER_INIT(sbase + 56, 1);                // done
    }
    __syncthreads();
    uint32_t tmem;
    asm volatile("ld.shared.b32 %0, [%1];" : "=r"(tmem) : "r"(sbase));

    const int nchunks = Kd / 64;

    if (tid == 0) {
        auto issue = [&](int c, int s) {
            const uint32_t St = sbase + 1024 + (uint32_t)s * GSTAGE;
            const uint32_t fb = sbase + 8 + s * 8;
            MBARRIER_EXPECT_TX(fb, 65536u);
            CP_BULK(St,         (const char*)Ahi + ((size_t)c * Md + m0) * 128, 16384u, fb);
            CP_BULK(St + 16384, (const char*)Alo + ((size_t)c * Md + m0) * 128, 16384u, fb);
            CP_BULK(St + 32768, (const char*)Bhi + ((size_t)c * Nd + n0) * 128, 16384u, fb);
            CP_BULK(St + 49152, (const char*)Blo + ((size_t)c * Nd + n0) * 128, 16384u, fb);
        };
        const int pro = (nchunks < 3) ? nchunks : 3;
        for (int s = 0; s < pro; s++) issue(s, s);

        for (int c = 0; c < nchunks; c++) {
            const int s = c % 3;
            MBARRIER_WAIT_PARITY(sbase + 8 + s * 8, (uint32_t)((c / 3) & 1));
            const uint32_t St = sbase + 1024 + (uint32_t)s * GSTAGE;
            const uint64_t ah = MAKE_SMEM_DESC(St);
            const uint64_t al = ah + (16384 >> 4);
            const uint64_t bh = ah + (32768 >> 4);
            const uint64_t bl = ah + (49152 >> 4);
#pragma unroll
            for (int t = 0; t < 3; t++) {
                const uint64_t ad = (t == 1) ? al : ah;
                const uint64_t bd = (t == 2) ? bl : bh;
#pragma unroll
                for (int kk = 0; kk < 4; kk++)
                    mma_f16_ss(tmem, ad + kk * 2, bd + kk * 2, GEMM_IDESC_N128,
                               (c > 0) || (t > 0) || (kk > 0));
            }
            TCGEN05_COMMIT(sbase + 32 + s * 8);
            if (c + 3 < nchunks) {
                MBARRIER_WAIT_PARITY(sbase + 32 + s * 8, (uint32_t)((c / 3) & 1));
                issue(c + 3, s);
            }
        }
        TCGEN05_COMMIT(sbase + 56);                  // orders ALL prior MMAs
        MBARRIER_WAIT_PARITY(sbase + 56, 0u);
    }
    __syncthreads();
    TCGEN05_FENCE_AFTER();

    {
        const int lane = tid & 31;
        const int rrow = m0 + wid * 32 + lane;
        float* crow = C + (size_t)rrow * Nd + n0;
        const float* extra = nullptr;
        if (rowsrc) {
            int rs = rowsrc[rrow];
            if (rs >= 0) extra = addsrc + (size_t)rs * Nd + n0;
        }
#pragma unroll
        for (int cb = 0; cb < 8; cb++) {
            uint32_t r[16];
            TCGEN05_LD_32X32B_X16(r, tmem + cb * 16);
            TCGEN05_WAIT_LD();
            const float* bia = bias + n0 + cb * 16;
            float* cp = crow + cb * 16;
#pragma unroll
            for (int jj = 0; jj < 16; jj += 4) {
                float4 v;
                v.x = __uint_as_float(r[jj+0]) + bia[jj+0];
                v.y = __uint_as_float(r[jj+1]) + bia[jj+1];
                v.z = __uint_as_float(r[jj+2]) + bia[jj+2];
                v.w = __uint_as_float(r[jj+3]) + bia[jj+3];
                if (extra) {
                    float4 e = *(const float4*)(extra + cb * 16 + jj);
                    v.x += e.x; v.y += e.y; v.z += e.z; v.w += e.w;
                }
                if (gelu_act) {
                    v.x = gelu_f(v.x); v.y = gelu_f(v.y);
                    v.z = gelu_f(v.z); v.w = gelu_f(v.w);
                }
                *(float4*)(cp + jj) = v;
                if (Chi) {
                    __nv_bfloat16 h0,l0,h1,l1,h2,l2,h3,l3;
                    split_one(v.x,h0,l0); split_one(v.y,h1,l1);
                    split_one(v.z,h2,l2); split_one(v.w,h3,l3);
                    const size_t o = chunk_off((size_t)Md, rrow, n0 + cb * 16 + jj);
                    *(uint2*)(Chi + o) = make_uint2(pack_bf2(h0,h1), pack_bf2(h2,h3));
                    *(uint2*)(Clo + o) = make_uint2(pack_bf2(l0,l1), pack_bf2(l2,l3));
                }
            }
        }
        TCGEN05_FENCE_BEFORE();
    }
    __syncthreads();
    if (tid == 0) {
#pragma unroll
        for (int s = 0; s < 3; s++) {
            MBARRIER_INVAL(sbase + 8  + s * 8);
            MBARRIER_INVAL(sbase + 32 + s * 8);
        }
        MBARRIER_INVAL(sbase + 56);
    }
    if (wid == 0) TCGEN05_DEALLOC(tmem, 128);
#else
    // SIMT fallback (never executed on GB300; kept merely compilable)
    const int tid = threadIdx.x;
    int gi = blockIdx.y * 128 * Nd + blockIdx.x * 128 + tid;
    if (gi < Md * Nd) C[gi] = bias ? bias[(blockIdx.x * 128 + tid) % Nd] : 0.f;
    (void)Ahi; (void)Alo; (void)Bhi; (void)Blo; (void)Chi; (void)Clo;
    (void)Kd; (void)gelu_act; (void)addsrc; (void)rowsrc;
#endif
}

// ---------------- tcgen05 flash attention (prefetched K/V) -------------------
#define S_QHI 1024
#define S_QLO (S_QHI+16384)
#define S_KHI (S_QLO+16384)
#define S_VT  (S_KHI+16384)
#define S_PT  (S_VT+16384)
#define ATT_SMEM (S_PT+32768)     // 99328 B
#define S_RED0 S_PT
#define S_RED1 (S_PT+512)

#if HAS_TCGEN05
// [128 rows x 64] fp32 tile -> scaled hi/lo bf16, SW128 (128B rows)
__device__ __forceinline__ void att_load_split(const float* src_base, char* hi_buf, char* lo_buf,
                                               float scale, int tid) {
    const int r = tid >> 1, seg = tid & 1;
    const float* src = src_base + (size_t)r * NQKV + seg * 32;
#pragma unroll
    for (int u = 0; u < 4; u++) {
        float4 a = ((const float4*)src)[2*u];
        float4 c = ((const float4*)src)[2*u+1];
        float v[8] = {a.x, a.y, a.z, a.w, c.x, c.y, c.z, c.w};
        uint32_t hw[4], lw[4];
#pragma unroll
        for (int p = 0; p < 4; p++) {
            float x0 = v[2*p] * scale, x1 = v[2*p+1] * scale;
            __nv_bfloat16 h0, h1, l0, l1;
            split_one(x0, h0, l0); split_one(x1, h1, l1);
            hw[p] = pack_bf2(h0, h1);
            lw[p] = pack_bf2(l0, l1);
        }
        uint32_t off = SMEM_SWIZZLE_128B((uint32_t)(r * 128 + seg * 64 + u * 16));
        *(uint4*)(hi_buf + off) = make_uint4(hw[0], hw[1], hw[2], hw[3]);
        *(uint4*)(lo_buf + off) = make_uint4(lw[0], lw[1], lw[2], lw[3]);
    }
}
#endif

__global__ __launch_bounds__(256, 2)
void attn_tc(const float* __restrict__ qkv,
             __nv_bfloat16* __restrict__ ctx_hi, __nv_bfloat16* __restrict__ ctx_lo) {
#if HAS_TCGEN05
    extern __shared__ __align__(1024) char smem[];
    const uint32_t sbase = smem_u32(smem);
    const int tid = threadIdx.x, wid = tid >> 5, lane = tid & 31;
    const int half = wid >> 2, sp = wid & 3;
    const int row_g = sp * 32 + lane;
    const int qt = blockIdx.x, h = blockIdx.y, b = blockIdx.z;

    if (wid == 0) { TCGEN05_ALLOC(sbase, 256); TCGEN05_RELINQ(); }
    if (tid == 0) { MBARRIER_INIT(sbase + 8, 1); MBARRIER_INIT(sbase + 16, 1); }
    __syncthreads();
    uint32_t tmem;
    asm volatile("ld.shared.b32 %0, [%1];" : "=r"(tmem) : "r"(sbase));
    const uint32_t tmem_S = tmem, tmem_O = tmem + 128;

    att_load_split(qkv + ((size_t)(b*SS + qt*128)) * NQKV + h*HDD,
                   smem + S_QHI, smem + S_QLO, 0.18033688011112042f, tid);

    const int kr = tid >> 1, kseg = tid & 1;
    const int kvp = (tid >> 2) * 2, dseg = (tid & 3) * 16;
    uint32_t pk[16], pv[16];

    auto prefetch_k = [&](int j) {
        const float* src = qkv + ((size_t)(b*SS + j*128 + kr)) * NQKV + HH + h*HDD + kseg * 32;
#pragma unroll
        for (int u = 0; u < 4; u++) {
            float4 a = ((const float4*)src)[2*u];
            float4 c = ((const float4*)src)[2*u+1];
            pk[u*4+0] = pack_bf2(__float2bfloat16(a.x), __float2bfloat16(a.y));
            pk[u*4+1] = pack_bf2(__float2bfloat16(a.z), __float2bfloat16(a.w));
            pk[u*4+2] = pack_bf2(__float2bfloat16(c.x), __float2bfloat16(c.y));
            pk[u*4+3] = pack_bf2(__float2bfloat16(c.z), __float2bfloat16(c.w));
        }
    };
    auto prefetch_v = [&](int j) {
        const float* s0 = qkv + ((size_t)(b*SS + j*128 + kvp    )) * NQKV + 2*HH + h*HDD + dseg;
        const float* s1 = qkv + ((size_t)(b*SS + j*128 + kvp + 1)) * NQKV + 2*HH + h*HDD + dseg;
#pragma unroll
        for (int u = 0; u < 4; u++) {
            float4 a0 = ((const float4*)s0)[u];
            float4 a1 = ((const float4*)s1)[u];
            __half2 q0 = __floats2half2_rn(a0.x, a1.x);
            __half2 q1 = __floats2half2_rn(a0.y, a1.y);
            __half2 q2 = __floats2half2_rn(a0.z, a1.z);
            __half2 q3 = __floats2half2_rn(a0.w, a1.w);
            pv[u*4+0] = *(uint32_t*)&q0; pv[u*4+1] = *(uint32_t*)&q1;
            pv[u*4+2] = *(uint32_t*)&q2; pv[u*4+3] = *(uint32_t*)&q3;
        }
    };

    prefetch_k(0); prefetch_v(0);

    float rsum = 0.f;
    int ps = 0, po = 0;

    for (int j = 0; j < 4; j++) {
        if (j > 0) { MBARRIER_WAIT_PARITY(sbase + 16, po); po ^= 1; }

#pragma unroll
        for (int u = 0; u < 4; u++) {
            uint32_t off = SMEM_SWIZZLE_128B((uint32_t)(kr * 128 + kseg * 64 + u * 16));
            *(uint4*)(smem + S_KHI + off) = make_uint4(pk[u*4+0], pk[u*4+1], pk[u*4+2], pk[u*4+3]);
        }
#pragma unroll
        for (int u = 0; u < 4; u++) {
#pragma unroll
            for (int e = 0; e < 4; e++) {
                int d = dseg + u*4 + e;
                uint32_t boff = (uint32_t)(((d >> 3) + (kvp >> 6) * 8) * 1024 + (d & 7) * 128 + (kvp & 63) * 2);
                *(uint32_t*)(smem + S_VT + SMEM_SWIZZLE_128B(boff)) = pv[u*4+e];
            }
        }
        FENCE_PROXY_ASYNC();
        __syncthreads();

        if (wid == 0 && elect_one_pred()) {
            const uint64_t qh = MAKE_SMEM_DESC(sbase + S_QHI);
            const uint64_t ql = MAKE_SMEM_DESC(sbase + S_QLO);
            const uint64_t kh = MAKE_SMEM_DESC(sbase + S_KHI);
#pragma unroll
            for (int t = 0; t < 2; t++) {
                uint64_t ad = (t == 1) ? ql : qh;
#pragma unroll
                for (int kk = 0; kk < 4; kk++)
                    mma_f16_ss(tmem_S, ad + kk*2, kh + kk*2, GEMM_IDESC_N128, (t > 0) || (kk > 0));
            }
            TCGEN05_COMMIT(sbase + 8);
        }

        if (j < 3) { prefetch_k(j+1); prefetch_v(j+1); }

        MBARRIER_WAIT_PARITY(sbase + 8, ps); ps ^= 1;
        TCGEN05_FENCE_AFTER();

        {
            char* Pb = smem + S_PT;
#pragma unroll
            for (int g = 0; g < 2; g++) {
                uint32_t r[32];
                TCGEN05_LD_32X32B_X32(r, tmem_S + half*64 + g*32);
                TCGEN05_WAIT_LD();
#pragma unroll
                for (int u = 0; u < 16; u++) {
                    float s0 = fminf(__uint_as_float(r[2*u]),   14.f);
                    float s1 = fminf(__uint_as_float(r[2*u+1]), 14.f);
                    uint32_t p2 = exp2_f16x2(s0, s1);
                    float2 f = __half22float2(*reinterpret_cast<__half2*>(&p2));
                    rsum += f.x + f.y;
                    int c = half*64 + g*32 + 2*u;
                    uint32_t boff = (uint32_t)(((row_g >> 3) + (c >> 6) * 16) * 1024 + (row_g & 7) * 128 + (c & 63) * 2);
                    *(uint32_t*)(Pb + SMEM_SWIZZLE_128B(boff)) = p2;
                }
            }
        }
        TCGEN05_FENCE_BEFORE();
        FENCE_PROXY_ASYNC();
        __syncthreads();

        if (wid == 0 && elect_one_pred()) {
            const uint64_t pd = MAKE_SMEM_DESC(sbase + S_PT);
            const uint64_t vd = MAKE_SMEM_DESC(sbase + S_VT);
#pragma unroll
            for (int ks = 0; ks < 8; ks++)
                mma_f16_ss(tmem_O,
                           pd + (uint64_t)(ks >> 2) * 1024 + (ks & 3) * 2,
                           vd + (uint64_t)(ks >> 2) * 512  + (ks & 3) * 2,
                           PV_IDESC, (j > 0) || (ks > 0));
            TCGEN05_COMMIT(sbase + 16);
        }
    }

    MBARRIER_WAIT_PARITY(sbase + 16, po);
    TCGEN05_FENCE_AFTER();

    float* red0 = (float*)(smem + S_RED0);
    float* red1 = (float*)(smem + S_RED1);
    if (half == 0) red0[row_g] = rsum; else red1[row_g] = rsum;
    __syncthreads();
    const float inv = 1.f / (red0[row_g] + red1[row_g]);

    uint32_t o[32];
    TCGEN05_LD_32X32B_X32(o, tmem_O + half * 32);
    TCGEN05_WAIT_LD();
    const int grow = b*SS + qt*128 + row_g;
#pragma unroll
    for (int u = 0; u < 8; u++) {
        float v0 = __uint_as_float(o[4*u+0]) * inv;
        float v1 = __uint_as_float(o[4*u+1]) * inv;
        float v2 = __uint_as_float(o[4*u+2]) * inv;
        float v3 = __uint_as_float(o[4*u+3]) * inv;
        __nv_bfloat16 h0,l0,h1,l1,h2,l2,h3,l3;
        split_one(v0,h0,l0); split_one(v1,h1,l1);
        split_one(v2,h2,l2); split_one(v3,h3,l3);
        const size_t oo = chunk_off((size_t)MM, grow, h*HDD + half*32 + u*4);
        *(uint2*)(ctx_hi + oo) = make_uint2(pack_bf2(h0,h1), pack_bf2(h2,h3));
        *(uint2*)(ctx_lo + oo) = make_uint2(pack_bf2(l0,l1), pack_bf2(l2,l3));
    }
    TCGEN05_FENCE_BEFORE();
    __syncthreads();
    if (tid == 0) { MBARRIER_INVAL(sbase + 8); MBARRIER_INVAL(sbase + 16); }
    if (wid == 0) TCGEN05_DEALLOC(tmem, 256);
#endif
}

// ---------------- residual + layernorm --------------------------------------
__device__ __forceinline__ float blockReduceSum(float val) {
    __shared__ float sm[32];
#pragma unroll
    for (int off = 16; off; off >>= 1) val += __shfl_xor_sync(0xffffffffu, val, off);
    __syncthreads();
    if ((threadIdx.x & 31) == 0) sm[threadIdx.x >> 5] = val;
    __syncthreads();
    if (threadIdx.x < 32) {
        float v = (threadIdx.x < (blockDim.x >> 5)) ? sm[threadIdx.x] : 0.f;
#pragma unroll
        for (int off = 16; off; off >>= 1) v += __shfl_xor_sync(0xffffffffu, v, off);
        if (threadIdx.x == 0) sm[0] = v;
    }
    __syncthreads();
    return sm[0];
}

__global__ __launch_bounds__(256)
void ln_kernel(const float* __restrict__ proj, const float* __restrict__ res,
               const float* __restrict__ gw, const float* __restrict__ bw,
               float* __restrict__ out) {
    int m = blockIdx.x, t = threadIdx.x;
    const float* p = proj + (size_t)m * HH;
    const float* r = res  + (size_t)m * HH;
    float x0 = p[t]     + r[t];
    float x1 = p[t+256] + r[t+256];
    float x2 = p[t+512] + r[t+512];
    float mu  = blockReduceSum(x0 + x1 + x2) * (1.f/HH);
    float d0 = x0 - mu, d1 = x1 - mu, d2 = x2 - mu;
    float var = blockReduceSum(d0*d0 + d1*d1 + d2*d2) * (1.f/HH);
    float inv = rsqrtf(var + 1e-12f);
    float* o = out + (size_t)m * HH;
    o[t]     = d0*inv*gw[t]     + bw[t];
    o[t+256] = d1*inv*gw[t+256] + bw[t+256];
    o[t+512] = d2*inv*gw[t+512] + bw[t+512];
}

// ---------------- launch ----------------------------------------------------
extern "C" void kernel_launch(void* const* d_in, const int* in_sizes, int n_in,
                              void* d_out, int out_size) {
    const float* hidden = (const float*)d_in[0];
    const float* colemb = (const float*)d_in[1];
    const int*   cat    = (const int*)  d_in[2];
    const int*   vmask  = (const int*)  d_in[3];
    const float* Wd = (const float*)d_in[4];  const float* bd = (const float*)d_in[5];
    const float* Wc = (const float*)d_in[6];  const float* bc = (const float*)d_in[7];
    const float* Wq = (const float*)d_in[8];  const float* bq = (const float*)d_in[9];
    const float* Wk = (const float*)d_in[10]; const float* bk = (const float*)d_in[11];
    const float* Wv = (const float*)d_in[12]; const float* bv = (const float*)d_in[13];
    const float* Wo = (const float*)d_in[14]; const float* bo = (const float*)d_in[15];
    const float* lng = (const float*)d_in[16]; const float* lnb = (const float*)d_in[17];
    float* out = (float*)d_out;

    __nv_bfloat16 *p_hid_hi, *p_hid_lo, *p_Wd_hi, *p_Wd_lo, *p_Wc_hi, *p_Wc_lo;
    __nv_bfloat16 *p_ce_hi, *p_ce_lo, *p_Wqkv_hi, *p_Wqkv_lo, *p_Wo_hi, *p_Wo_lo;
    __nv_bfloat16 *p_h_hi, *p_h_lo, *p_ctx_hi, *p_ctx_lo;
    float *p_colproj, *p_bcat, *p_zero, *p_bqkv, *p_h, *p_qkv, *p_proj;
    int *p_rowsrc;
    cudaGetSymbolAddress((void**)&p_hid_hi,  g_hid_hi);
    cudaGetSymbolAddress((void**)&p_hid_lo,  g_hid_lo);
    cudaGetSymbolAddress((void**)&p_Wd_hi,   g_Wd_hi);
    cudaGetSymbolAddress((void**)&p_Wd_lo,   g_Wd_lo);
    cudaGetSymbolAddress((void**)&p_Wc_hi,   g_Wc_hi);
    cudaGetSymbolAddress((void**)&p_Wc_lo,   g_Wc_lo);
    cudaGetSymbolAddress((void**)&p_ce_hi,   g_ce_hi);
    cudaGetSymbolAddress((void**)&p_ce_lo,   g_ce_lo);
    cudaGetSymbolAddress((void**)&p_colproj, g_colproj);
    cudaGetSymbolAddress((void**)&p_rowsrc,  g_rowsrc);
    cudaGetSymbolAddress((void**)&p_bcat,    g_bcat);
    cudaGetSymbolAddress((void**)&p_zero,    g_zero);
    cudaGetSymbolAddress((void**)&p_Wqkv_hi, g_Wqkv_hi);
    cudaGetSymbolAddress((void**)&p_Wqkv_lo, g_Wqkv_lo);
    cudaGetSymbolAddress((void**)&p_bqkv,    g_bqkv);
    cudaGetSymbolAddress((void**)&p_Wo_hi,   g_Wo_hi);
    cudaGetSymbolAddress((void**)&p_Wo_lo,   g_Wo_lo);
    cudaGetSymbolAddress((void**)&p_h,       g_h);
    cudaGetSymbolAddress((void**)&p_h_hi,    g_h_hi);
    cudaGetSymbolAddress((void**)&p_h_lo,    g_h_lo);
    cudaGetSymbolAddress((void**)&p_qkv,     g_qkv);
    cudaGetSymbolAddress((void**)&p_ctx_hi,  g_ctx_hi);
    cudaGetSymbolAddress((void**)&p_ctx_lo,  g_ctx_lo);
    cudaGetSymbolAddress((void**)&p_proj,    g_proj);

    cudaFuncSetAttribute(gemm_bf16x3, cudaFuncAttributeMaxDynamicSharedMemorySize, GEMM_SMEM_BYTES);
    cudaFuncSetAttribute(attn_tc, cudaFuncAttributeMaxDynamicSharedMemorySize, ATT_SMEM);

    // launch 0: merged prep (chunked layouts)
    prep_all<<<(NQKV*HH + 255)/256, 256>>>(Wd, bd, Wc, bc, Wq, bq, Wk, bk, Wv, bv,
                                           Wo, colemb, cat, vmask);
    // launch 1: split hidden (chunked)
    split_f32_ch<<<(MM*HH + 255)/256, 256>>>(hidden, p_hid_hi, p_hid_lo, MM, HH);

    // launch 2: colproj = masked(colemb) @ Wc^T
    gemm_bf16x3<<<dim3(HH/128, (BB*NCOLL)/128), 128, GEMM_SMEM_BYTES>>>(
        p_ce_hi, p_ce_lo, p_Wc_hi, p_Wc_lo, p_zero, p_colproj, nullptr, nullptr,
        BB*NCOLL, HH, HH, 0, nullptr, nullptr);

    // launch 3: h = gelu(hidden @ Wd^T + (bd+bc) + gather(colproj)); fused split
    gemm_bf16x3<<<dim3(HH/128, MM/128), 128, GEMM_SMEM_BYTES>>>(
        p_hid_hi, p_hid_lo, p_Wd_hi, p_Wd_lo, p_bcat, p_h, p_h_hi, p_h_lo,
        MM, HH, HH, 1, p_colproj, p_rowsrc);

    // launch 4: qkv = h @ Wqkv^T + bqkv
    gemm_bf16x3<<<dim3(NQKV/128, MM/128), 128, GEMM_SMEM_BYTES>>>(
        p_h_hi, p_h_lo, p_Wqkv_hi, p_Wqkv_lo, p_bqkv, p_qkv, nullptr, nullptr,
        MM, NQKV, HH, 0, nullptr, nullptr);

    // launch 5 (ncu capture slot): attention -> ctx hi/lo (chunked)
    attn_tc<<<dim3(SS/128, NHH, BB), 256, ATT_SMEM>>>(p_qkv, p_ctx_hi, p_ctx_lo);

    // launch 6: proj = ctx @ Wo^T + bo
    gemm_bf16x3<<<dim3(HH/128, MM/128), 128, GEMM_SMEM_BYTES>>>(
        p_ctx_hi, p_ctx_lo, p_Wo_hi, p_Wo_lo, bo, p_proj, nullptr, nullptr,
        MM, HH, HH, 0, nullptr, nullptr);

    // launch 7: out = LN(proj + h)
    ln_kernel<<<MM, 256>>>(p_proj, p_h, lng, lnb, out);
}

// round 17
// speedup vs baseline: 1.0898x; 1.0898x over previous
#include <cuda_runtime.h>
#include <cuda_bf16.h>
#include <cuda_fp16.h>
#include <math.h>
#include <stdint.h>

// Problem constants
#define BB    32
#define SS    512
#define HH    768
#define NHH   12
#define HDD   64
#define NCOLL 32
#define MM    (BB*SS)     // 16384 rows
#define NQKV  (3*HH)      // 2304

#if defined(__CUDA_ARCH__) && (defined(__CUDA_ARCH_FEAT_SM103_ALL) || defined(__CUDA_ARCH_FEAT_SM100_ALL) || defined(__CUDA_ARCH_SPECIFIC__))
#define HAS_TCGEN05 1
#else
#define HAS_TCGEN05 0
#endif

// ---------------- helpers ----------------------------------------------------
__device__ __forceinline__ uint32_t smem_u32(const void* p) {
    uint32_t a;
    asm("{ .reg .u64 t; cvta.to.shared.u64 t, %1; cvt.u32.u64 %0, t; }" : "=r"(a) : "l"(p));
    return a;
}
#define SMEM_SWIZZLE_128B(o) ((o) ^ (((o) >> 3) & 0x70))

// chunked+pre-swizzled gmem layout for bf16 GEMM operands:
// element (r,k) of an [R rows, K cols] array lives at
//   ((k>>6)*R + r)*64 + ((k&63) ^ ((r&7)<<3))          [element units]
__device__ __host__ __forceinline__ size_t chunk_off(size_t R, int r, int k) {
    return ((size_t)((unsigned)k >> 6) * R + (size_t)r) * 64
         + (size_t)((((unsigned)k) & 63u) ^ ((((unsigned)r) & 7u) << 3));
}

__device__ __forceinline__ uint32_t pack_bf2(__nv_bfloat16 a, __nv_bfloat16 b) {
    __nv_bfloat162 t; t.x = a; t.y = b;
    return *reinterpret_cast<uint32_t*>(&t);
}
__device__ __forceinline__ void split_one(float x, __nv_bfloat16& hi, __nv_bfloat16& lo) {
    __nv_bfloat16 h = __float2bfloat16(x);
    hi = h;
    lo = __float2bfloat16(x - __bfloat162float(h));
}
__device__ __forceinline__ float gelu_f(float x) {
    return 0.5f * x * (1.f + erff(x * 0.70710678118654752f));
}

#if HAS_TCGEN05
__device__ __forceinline__ uint32_t elect_one_pred() {
    uint32_t pred;
    asm volatile("{\n\t.reg .pred p;\n\telect.sync _|p, 0xFFFFFFFF;\n\tselp.b32 %0, 1, 0, p;\n\t}" : "=r"(pred));
    return pred;
}

static constexpr uint64_t SMEM_DESC_BASE_SW128 =
    (uint64_t(2) << 61) | (uint64_t(1) << 46) | (uint64_t(64) << 32) | (uint64_t(1) << 16);
#define MAKE_SMEM_DESC(base_addr) \
    (SMEM_DESC_BASE_SW128 | ((uint64_t)((base_addr) >> 4) & 0x3FFF))

#define FENCE_PROXY_ASYNC() \
    asm volatile("fence.proxy.async.shared::cta;" ::: "memory")

// bulk async copy, completion via mbarrier complete_tx
#define CP_BULK(dst_u32, src_ptr, bytes, mbar) \
    asm volatile("cp.async.bulk.shared::cluster.global.mbarrier::complete_tx::bytes [%0], [%1], %2, [%3];" \
        :: "r"((uint32_t)(dst_u32)), "l"(src_ptr), "r"((uint32_t)(bytes)), "r"((uint32_t)(mbar)) : "memory")
#define MBARRIER_EXPECT_TX(mbar, tx) \
    asm volatile("mbarrier.arrive.expect_tx.shared.b64 _, [%0], %1;" \
        :: "r"((uint32_t)(mbar)), "r"((uint32_t)(tx)) : "memory")

#define TCGEN05_ALLOC(smem_result_addr, nCols) \
    asm volatile("tcgen05.alloc.cta_group::1.sync.aligned.shared::cta.b32 [%0], %1;" \
        :: "r"((uint32_t)(smem_result_addr)), "r"((uint32_t)(nCols)) : "memory")
#define TCGEN05_DEALLOC(tmem_addr, nCols) \
    asm volatile("tcgen05.dealloc.cta_group::1.sync.aligned.b32 %0, %1;" :: "r"(tmem_addr), "r"((uint32_t)(nCols)))
#define TCGEN05_RELINQ() \
    asm volatile("tcgen05.relinquish_alloc_permit.cta_group::1.sync.aligned;")
#define TCGEN05_COMMIT(mbar) \
    asm volatile("tcgen05.commit.cta_group::1.mbarrier::arrive::one.shared::cluster.b64 [%0];" \
        :: "r"((uint32_t)(mbar)) : "memory")
#define TCGEN05_FENCE_AFTER()  asm volatile("tcgen05.fence::after_thread_sync;" ::: "memory")
#define TCGEN05_FENCE_BEFORE() asm volatile("tcgen05.fence::before_thread_sync;" ::: "memory")
#define TCGEN05_WAIT_LD() asm volatile("tcgen05.wait::ld.sync.aligned;" ::: "memory")

#define MBARRIER_INIT(mbar, count) \
    asm volatile("mbarrier.init.shared.b64 [%0], %1;" :: "r"((uint32_t)(mbar)), "r"((uint32_t)(count)) : "memory")
#define MBARRIER_INVAL(mbar) \
    asm volatile("mbarrier.inval.shared.b64 [%0];" :: "r"((uint32_t)(mbar)) : "memory")
#define MBARRIER_WAIT_PARITY(mbar_smem_addr, phase_parity) do { \
    uint32_t _mbar = (uint32_t)(mbar_smem_addr); \
    uint32_t _parity = (uint32_t)(phase_parity); \
    uint32_t _done; \
    asm volatile("{\n\t.reg .pred p;\n\t" \
        "mbarrier.try_wait.parity.acquire.cta.shared::cta.b64 p, [%1], %2;\n\t" \
        "selp.b32 %0, 1, 0, p;\n\t}" : "=r"(_done) : "r"(_mbar), "r"(_parity) : "memory"); \
    if (!_done) { \
        asm volatile("{\n\t.reg .pred P1;\n\t" \
            "WAIT_LOOP_%=:\n\t" \
            "mbarrier.try_wait.parity.acquire.cta.shared::cta.b64 P1, [%0], %1, 0x989680;\n\t" \
            "@P1 bra.uni WAIT_DONE_%=;\n\t" \
            "bra.uni WAIT_LOOP_%=;\n\t" \
            "WAIT_DONE_%=:\n\t}" :: "r"(_mbar), "r"(_parity) : "memory"); \
    } \
} while(0)

#define TCGEN05_LD_32X32B_X32(r, tmem_addr) \
    asm volatile("tcgen05.ld.sync.aligned.32x32b.x32.b32 " \
        "{%0, %1, %2, %3, %4, %5, %6, %7, %8, %9, %10, %11, %12, %13, %14, %15, " \
        " %16, %17, %18, %19, %20, %21, %22, %23, %24, %25, %26, %27, %28, %29, %30, %31}, [%32];" \
        : "=r"((r)[0]),  "=r"((r)[1]),  "=r"((r)[2]),  "=r"((r)[3]), \
          "=r"((r)[4]),  "=r"((r)[5]),  "=r"((r)[6]),  "=r"((r)[7]), \
          "=r"((r)[8]),  "=r"((r)[9]),  "=r"((r)[10]), "=r"((r)[11]), \
          "=r"((r)[12]), "=r"((r)[13]), "=r"((r)[14]), "=r"((r)[15]), \
          "=r"((r)[16]), "=r"((r)[17]), "=r"((r)[18]), "=r"((r)[19]), \
          "=r"((r)[20]), "=r"((r)[21]), "=r"((r)[22]), "=r"((r)[23]), \
          "=r"((r)[24]), "=r"((r)[25]), "=r"((r)[26]), "=r"((r)[27]), \
          "=r"((r)[28]), "=r"((r)[29]), "=r"((r)[30]), "=r"((r)[31]) \
        : "r"(tmem_addr))

#define TCGEN05_LD_32X32B_X16(r, tmem_addr) \
    asm volatile("tcgen05.ld.sync.aligned.32x32b.x16.b32 " \
        "{%0, %1, %2, %3, %4, %5, %6, %7, %8, %9, %10, %11, %12, %13, %14, %15}, [%16];" \
        : "=r"((r)[0]),  "=r"((r)[1]),  "=r"((r)[2]),  "=r"((r)[3]), \
          "=r"((r)[4]),  "=r"((r)[5]),  "=r"((r)[6]),  "=r"((r)[7]), \
          "=r"((r)[8]),  "=r"((r)[9]),  "=r"((r)[10]), "=r"((r)[11]), \
          "=r"((r)[12]), "=r"((r)[13]), "=r"((r)[14]), "=r"((r)[15]) \
        : "r"(tmem_addr))

__device__ __forceinline__ void mma_f16_ss(uint32_t d_tmem, uint64_t a_desc, uint64_t b_desc,
                                           uint32_t idesc, int enable_d) {
    asm volatile(
        "{\n\t.reg .pred p;\n\t"
        "setp.ne.u32 p, %5, 0;\n\t"
        "tcgen05.mma.cta_group::1.kind::f16 [%0], %1, %2, %3, {%4, %4, %4, %4}, p;\n\t}"
        :: "r"(d_tmem), "l"(a_desc), "l"(b_desc), "r"(idesc), "r"(0u), "r"((uint32_t)enable_d)
        : "memory");
}

// idesc: dtype F32, a/b BF16, M=128, N=128
#define GEMM_IDESC_N128 ((1u<<4) | (1u<<7) | (1u<<10) | ((128u/8u)<<17) | ((128u/16u)<<24))
// idesc: dtype F32, a/b F16, N=64, M=128 (K-major both sides)
#define PV_IDESC   ((1u<<4) | ((64u/8u)<<17) | ((128u/16u)<<24))

__device__ __forceinline__ uint32_t exp2_f16x2(float lo, float hi) {
    uint32_t p, r;
    asm("cvt.rn.f16x2.f32 %0, %1, %2;" : "=r"(p) : "f"(hi), "f"(lo));
    asm("ex2.approx.f16x2 %0, %1;" : "=r"(r) : "r"(p));
    return r;
}
#endif // HAS_TCGEN05

// ---------------- scratch (chunked bf16 arrays 128B-aligned for bulk TMA) -----
__device__ __align__(128) __nv_bfloat16 g_hid_hi[(size_t)MM*HH];
__device__ __align__(128) __nv_bfloat16 g_hid_lo[(size_t)MM*HH];
__device__ __align__(128) __nv_bfloat16 g_Wd_hi[(size_t)HH*HH];
__device__ __align__(128) __nv_bfloat16 g_Wd_lo[(size_t)HH*HH];
__device__ __align__(128) __nv_bfloat16 g_Wc_hi[(size_t)HH*HH];
__device__ __align__(128) __nv_bfloat16 g_Wc_lo[(size_t)HH*HH];
__device__ __align__(128) __nv_bfloat16 g_ce_hi[(size_t)BB*NCOLL*HH];
__device__ __align__(128) __nv_bfloat16 g_ce_lo[(size_t)BB*NCOLL*HH];
__device__ float         g_colproj[(size_t)BB*NCOLL*HH];
__device__ int           g_rowsrc[MM];
__device__ float         g_bcat[HH];
__device__ float         g_zero[HH];
__device__ __align__(128) __nv_bfloat16 g_Wqkv_hi[(size_t)NQKV*HH];
__device__ __align__(128) __nv_bfloat16 g_Wqkv_lo[(size_t)NQKV*HH];
__device__ float         g_bqkv[NQKV];
__device__ __align__(128) __nv_bfloat16 g_Wo_hi[(size_t)HH*HH];
__device__ __align__(128) __nv_bfloat16 g_Wo_lo[(size_t)HH*HH];
__device__ float         g_h[(size_t)MM*HH];
__device__ __align__(128) __nv_bfloat16 g_h_hi[(size_t)MM*HH];
__device__ __align__(128) __nv_bfloat16 g_h_lo[(size_t)MM*HH];
__device__ float         g_qkv[(size_t)MM*NQKV];
__device__ __align__(128) __nv_bfloat16 g_ctx_hi[(size_t)MM*HH];
__device__ __align__(128) __nv_bfloat16 g_ctx_lo[(size_t)MM*HH];
__device__ float         g_proj[(size_t)MM*HH];

// ---------------- merged prep (writes chunked layout) -------------------------
__global__ void prep_all(const float* __restrict__ Wd, const float* __restrict__ bd,
                         const float* __restrict__ Wc, const float* __restrict__ bc,
                         const float* __restrict__ Wq, const float* __restrict__ bq,
                         const float* __restrict__ Wk, const float* __restrict__ bk,
                         const float* __restrict__ Wv, const float* __restrict__ bv,
                         const float* __restrict__ Wo,
                         const float* __restrict__ colemb,
                         const int* __restrict__ cat, const int* __restrict__ vmask) {
    int i = blockIdx.x * blockDim.x + threadIdx.x;
    if (i < NQKV * HH) {
        int n = i / HH, k = i % HH;
        float v;
        if (n < HH)        v = Wq[n*HH + k];
        else if (n < 2*HH) v = Wk[(n-HH)*HH + k];
        else               v = Wv[(n-2*HH)*HH + k];
        size_t o = chunk_off(NQKV, n, k);
        split_one(v, g_Wqkv_hi[o], g_Wqkv_lo[o]);
    }
    if (i < HH*HH) {
        int n = i / HH, k = i % HH;
        size_t o = chunk_off(HH, n, k);
        split_one(Wd[i], g_Wd_hi[o], g_Wd_lo[o]);
        split_one(Wc[i], g_Wc_hi[o], g_Wc_lo[o]);
        split_one(Wo[i], g_Wo_hi[o], g_Wo_lo[o]);
    }
    if (i < BB*NCOLL*HH) {
        int bc_ = i / HH, k = i % HH;
        float v = (cat[bc_] == 1) ? colemb[i] : 0.f;
        size_t o = chunk_off(BB*NCOLL, bc_, k);
        split_one(v, g_ce_hi[o], g_ce_lo[o]);
    }
    if (i < MM) {
        int b = i / SS;
        int idx = vmask[i];
        int rs = -1;
        if (idx > 0 && cat[b*NCOLL + idx - 1] == 1) rs = b*NCOLL + idx - 1;
        g_rowsrc[i] = rs;
    }
    if (i < NQKV) {
        float v;
        if (i < HH)        v = bq[i];
        else if (i < 2*HH) v = bk[i-HH];
        else               v = bv[i-2*HH];
        g_bqkv[i] = v;
    }
    if (i < HH) g_bcat[i] = bd[i] + bc[i];
}

__global__ void split_f32_ch(const float* __restrict__ x, __nv_bfloat16* __restrict__ hi,
                             __nv_bfloat16* __restrict__ lo, int R, int K) {
    int i = blockIdx.x * blockDim.x + threadIdx.x;
    if (i < R * K) {
        int r = i / K, k = i % K;
        size_t o = chunk_off((size_t)R, r, k);
        split_one(x[i], hi[o], lo[o]);
    }
}

// ---------------- tcgen05 bf16x3-split GEMM, warp-specialized TMA pipeline ----
// 128x128 tile; chunk = K-64 slice; stage = Ahi|Alo|Bhi|Blo (64KB, one 16KB
// bulk TMA per array). Thread 32 (warp 1) = TMA producer; thread 0 (warp 0) =
// MMA issuer; all 128 threads epilogue. 3 stages = 193KB -> 1 CTA/SM.
#define GSTAGE 65536
#define GEMM_SMEM_BYTES (1024 + 3*GSTAGE)

__global__ __launch_bounds__(128, 1)
void gemm_bf16x3(const __nv_bfloat16* __restrict__ Ahi, const __nv_bfloat16* __restrict__ Alo,
                 const __nv_bfloat16* __restrict__ Bhi, const __nv_bfloat16* __restrict__ Blo,
                 const float* __restrict__ bias, float* __restrict__ C,
                 __nv_bfloat16* __restrict__ Chi, __nv_bfloat16* __restrict__ Clo,
                 int Md, int Nd, int Kd, int gelu_act,
                 const float* __restrict__ addsrc, const int* __restrict__ rowsrc) {
#if HAS_TCGEN05
    extern __shared__ __align__(1024) char smem[];
    const uint32_t sbase = smem_u32(smem);
    const int tid = threadIdx.x;
    const int wid = tid >> 5;
    const int m0 = blockIdx.y * 128;
    const int n0 = blockIdx.x * 128;

    if (wid == 0) { TCGEN05_ALLOC(sbase, 128); TCGEN05_RELINQ(); }
    if (tid == 0) {
#pragma unroll
        for (int s = 0; s < 3; s++) {
            MBARRIER_INIT(sbase + 8  + s * 8, 1);    // full[s]  (expect_tx arrive + tx)
            MBARRIER_INIT(sbase + 32 + s * 8, 1);    // empty[s] (MMA commit)
        }
        MBARRIER_INIT(sbase + 56, 1);                // done
    }
    __syncthreads();
    uint32_t tmem;
    asm volatile("ld.shared.b32 %0, [%1];" : "=r"(tmem) : "r"(sbase));

    const int nchunks = Kd / 64;

    if (tid == 32) {
        // ---------------- TMA producer (warp 1, single thread) -------------
        for (int c = 0; c < nchunks; c++) {
            const int s = c % 3;
            if (c >= 3)
                MBARRIER_WAIT_PARITY(sbase + 32 + s * 8, (uint32_t)((c / 3 - 1) & 1));
            const uint32_t St = sbase + 1024 + (uint32_t)s * GSTAGE;
            const uint32_t fb = sbase + 8 + s * 8;
            MBARRIER_EXPECT_TX(fb, 65536u);
            CP_BULK(St,         (const char*)Ahi + ((size_t)c * Md + m0) * 128, 16384u, fb);
            CP_BULK(St + 16384, (const char*)Alo + ((size_t)c * Md + m0) * 128, 16384u, fb);
            CP_BULK(St + 32768, (const char*)Bhi + ((size_t)c * Nd + n0) * 128, 16384u, fb);
            CP_BULK(St + 49152, (const char*)Blo + ((size_t)c * Nd + n0) * 128, 16384u, fb);
        }
    } else if (tid == 0) {
        // ---------------- MMA issuer (warp 0, single thread) ----------------
        for (int c = 0; c < nchunks; c++) {
            const int s = c % 3;
            MBARRIER_WAIT_PARITY(sbase + 8 + s * 8, (uint32_t)((c / 3) & 1));
            const uint32_t St = sbase + 1024 + (uint32_t)s * GSTAGE;
            const uint64_t ah = MAKE_SMEM_DESC(St);
            const uint64_t al = ah + (16384 >> 4);
            const uint64_t bh = ah + (32768 >> 4);
            const uint64_t bl = ah + (49152 >> 4);
#pragma unroll
            for (int t = 0; t < 3; t++) {
                const uint64_t ad = (t == 1) ? al : ah;
                const uint64_t bd = (t == 2) ? bl : bh;
#pragma unroll
                for (int kk = 0; kk < 4; kk++)
                    mma_f16_ss(tmem, ad + kk * 2, bd + kk * 2, GEMM_IDESC_N128,
                               (c > 0) || (t > 0) || (kk > 0));
            }
            TCGEN05_COMMIT(sbase + 32 + s * 8);
        }
        TCGEN05_COMMIT(sbase + 56);                  // orders ALL prior MMAs
        MBARRIER_WAIT_PARITY(sbase + 56, 0u);
    }
    __syncthreads();
    TCGEN05_FENCE_AFTER();

    {
        const int lane = tid & 31;
        const int rrow = m0 + wid * 32 + lane;
        float* crow = C + (size_t)rrow * Nd + n0;
        const float* extra = nullptr;
        if (rowsrc) {
            int rs = rowsrc[rrow];
            if (rs >= 0) extra = addsrc + (size_t)rs * Nd + n0;
        }
#pragma unroll
        for (int cb = 0; cb < 8; cb++) {
            uint32_t r[16];
            TCGEN05_LD_32X32B_X16(r, tmem + cb * 16);
            TCGEN05_WAIT_LD();
            const float* bia = bias + n0 + cb * 16;
            float* cp = crow + cb * 16;
#pragma unroll
            for (int jj = 0; jj < 16; jj += 4) {
                float4 v;
                v.x = __uint_as_float(r[jj+0]) + bia[jj+0];
                v.y = __uint_as_float(r[jj+1]) + bia[jj+1];
                v.z = __uint_as_float(r[jj+2]) + bia[jj+2];
                v.w = __uint_as_float(r[jj+3]) + bia[jj+3];
                if (extra) {
                    float4 e = *(const float4*)(extra + cb * 16 + jj);
                    v.x += e.x; v.y += e.y; v.z += e.z; v.w += e.w;
                }
                if (gelu_act) {
                    v.x = gelu_f(v.x); v.y = gelu_f(v.y);
                    v.z = gelu_f(v.z); v.w = gelu_f(v.w);
                }
                *(float4*)(cp + jj) = v;
                if (Chi) {
                    __nv_bfloat16 h0,l0,h1,l1,h2,l2,h3,l3;
                    split_one(v.x,h0,l0); split_one(v.y,h1,l1);
                    split_one(v.z,h2,l2); split_one(v.w,h3,l3);
                    const size_t o = chunk_off((size_t)Md, rrow, n0 + cb * 16 + jj);
                    *(uint2*)(Chi + o) = make_uint2(pack_bf2(h0,h1), pack_bf2(h2,h3));
                    *(uint2*)(Clo + o) = make_uint2(pack_bf2(l0,l1), pack_bf2(l2,l3));
                }
            }
        }
        TCGEN05_FENCE_BEFORE();
    }
    __syncthreads();
    if (tid == 0) {
#pragma unroll
        for (int s = 0; s < 3; s++) {
            MBARRIER_INVAL(sbase + 8  + s * 8);
            MBARRIER_INVAL(sbase + 32 + s * 8);
        }
        MBARRIER_INVAL(sbase + 56);
    }
    if (wid == 0) TCGEN05_DEALLOC(tmem, 128);
#else
    // SIMT fallback (never executed on GB300; kept merely compilable)
    const int tid = threadIdx.x;
    int gi = blockIdx.y * 128 * Nd + blockIdx.x * 128 + tid;
    if (gi < Md * Nd) C[gi] = bias ? bias[(blockIdx.x * 128 + tid) % Nd] : 0.f;
    (void)Ahi; (void)Alo; (void)Bhi; (void)Blo; (void)Chi; (void)Clo;
    (void)Kd; (void)gelu_act; (void)addsrc; (void)rowsrc;
#endif
}

// ---------------- tcgen05 flash attention (prefetched K/V) -------------------
#define S_QHI 1024
#define S_QLO (S_QHI+16384)
#define S_KHI (S_QLO+16384)
#define S_VT  (S_KHI+16384)
#define S_PT  (S_VT+16384)
#define ATT_SMEM (S_PT+32768)     // 99328 B
#define S_RED0 S_PT
#define S_RED1 (S_PT+512)

#if HAS_TCGEN05
// [128 rows x 64] fp32 tile -> scaled hi/lo bf16, SW128 (128B rows)
__device__ __forceinline__ void att_load_split(const float* src_base, char* hi_buf, char* lo_buf,
                                               float scale, int tid) {
    const int r = tid >> 1, seg = tid & 1;
    const float* src = src_base + (size_t)r * NQKV + seg * 32;
#pragma unroll
    for (int u = 0; u < 4; u++) {
        float4 a = ((const float4*)src)[2*u];
        float4 c = ((const float4*)src)[2*u+1];
        float v[8] = {a.x, a.y, a.z, a.w, c.x, c.y, c.z, c.w};
        uint32_t hw[4], lw[4];
#pragma unroll
        for (int p = 0; p < 4; p++) {
            float x0 = v[2*p] * scale, x1 = v[2*p+1] * scale;
            __nv_bfloat16 h0, h1, l0, l1;
            split_one(x0, h0, l0); split_one(x1, h1, l1);
            hw[p] = pack_bf2(h0, h1);
            lw[p] = pack_bf2(l0, l1);
        }
        uint32_t off = SMEM_SWIZZLE_128B((uint32_t)(r * 128 + seg * 64 + u * 16));
        *(uint4*)(hi_buf + off) = make_uint4(hw[0], hw[1], hw[2], hw[3]);
        *(uint4*)(lo_buf + off) = make_uint4(lw[0], lw[1], lw[2], lw[3]);
    }
}
#endif

__global__ __launch_bounds__(256, 2)
void attn_tc(const float* __restrict__ qkv,
             __nv_bfloat16* __restrict__ ctx_hi, __nv_bfloat16* __restrict__ ctx_lo) {
#if HAS_TCGEN05
    extern __shared__ __align__(1024) char smem[];
    const uint32_t sbase = smem_u32(smem);
    const int tid = threadIdx.x, wid = tid >> 5, lane = tid & 31;
    const int half = wid >> 2, sp = wid & 3;
    const int row_g = sp * 32 + lane;
    const int qt = blockIdx.x, h = blockIdx.y, b = blockIdx.z;

    if (wid == 0) { TCGEN05_ALLOC(sbase, 256); TCGEN05_RELINQ(); }
    if (tid == 0) { MBARRIER_INIT(sbase + 8, 1); MBARRIER_INIT(sbase + 16, 1); }
    __syncthreads();
    uint32_t tmem;
    asm volatile("ld.shared.b32 %0, [%1];" : "=r"(tmem) : "r"(sbase));
    const uint32_t tmem_S = tmem, tmem_O = tmem + 128;

    att_load_split(qkv + ((size_t)(b*SS + qt*128)) * NQKV + h*HDD,
                   smem + S_QHI, smem + S_QLO, 0.18033688011112042f, tid);

    const int kr = tid >> 1, kseg = tid & 1;
    const int kvp = (tid >> 2) * 2, dseg = (tid & 3) * 16;
    uint32_t pk[16], pv[16];

    auto prefetch_k = [&](int j) {
        const float* src = qkv + ((size_t)(b*SS + j*128 + kr)) * NQKV + HH + h*HDD + kseg * 32;
#pragma unroll
        for (int u = 0; u < 4; u++) {
            float4 a = ((const float4*)src)[2*u];
            float4 c = ((const float4*)src)[2*u+1];
            pk[u*4+0] = pack_bf2(__float2bfloat16(a.x), __float2bfloat16(a.y));
            pk[u*4+1] = pack_bf2(__float2bfloat16(a.z), __float2bfloat16(a.w));
            pk[u*4+2] = pack_bf2(__float2bfloat16(c.x), __float2bfloat16(c.y));
            pk[u*4+3] = pack_bf2(__float2bfloat16(c.z), __float2bfloat16(c.w));
        }
    };
    auto prefetch_v = [&](int j) {
        const float* s0 = qkv + ((size_t)(b*SS + j*128 + kvp    )) * NQKV + 2*HH + h*HDD + dseg;
        const float* s1 = qkv + ((size_t)(b*SS + j*128 + kvp + 1)) * NQKV + 2*HH + h*HDD + dseg;
#pragma unroll
        for (int u = 0; u < 4; u++) {
            float4 a0 = ((const float4*)s0)[u];
            float4 a1 = ((const float4*)s1)[u];
            __half2 q0 = __floats2half2_rn(a0.x, a1.x);
            __half2 q1 = __floats2half2_rn(a0.y, a1.y);
            __half2 q2 = __floats2half2_rn(a0.z, a1.z);
            __half2 q3 = __floats2half2_rn(a0.w, a1.w);
            pv[u*4+0] = *(uint32_t*)&q0; pv[u*4+1] = *(uint32_t*)&q1;
            pv[u*4+2] = *(uint32_t*)&q2; pv[u*4+3] = *(uint32_t*)&q3;
        }
    };

    prefetch_k(0); prefetch_v(0);

    float rsum = 0.f;
    int ps = 0, po = 0;

    for (int j = 0; j < 4; j++) {
        if (j > 0) { MBARRIER_WAIT_PARITY(sbase + 16, po); po ^= 1; }

#pragma unroll
        for (int u = 0; u < 4; u++) {
            uint32_t off = SMEM_SWIZZLE_128B((uint32_t)(kr * 128 + kseg * 64 + u * 16));
            *(uint4*)(smem + S_KHI + off) = make_uint4(pk[u*4+0], pk[u*4+1], pk[u*4+2], pk[u*4+3]);
        }
#pragma unroll
        for (int u = 0; u < 4; u++) {
#pragma unroll
            for (int e = 0; e < 4; e++) {
                int d = dseg + u*4 + e;
                uint32_t boff = (uint32_t)(((d >> 3) + (kvp >> 6) * 8) * 1024 + (d & 7) * 128 + (kvp & 63) * 2);
                *(uint32_t*)(smem + S_VT + SMEM_SWIZZLE_128B(boff)) = pv[u*4+e];
            }
        }
        FENCE_PROXY_ASYNC();
        __syncthreads();

        if (wid == 0 && elect_one_pred()) {
            const uint64_t qh = MAKE_SMEM_DESC(sbase + S_QHI);
            const uint64_t ql = MAKE_SMEM_DESC(sbase + S_QLO);
            const uint64_t kh = MAKE_SMEM_DESC(sbase + S_KHI);
#pragma unroll
            for (int t = 0; t < 2; t++) {
                uint64_t ad = (t == 1) ? ql : qh;
#pragma unroll
                for (int kk = 0; kk < 4; kk++)
                    mma_f16_ss(tmem_S, ad + kk*2, kh + kk*2, GEMM_IDESC_N128, (t > 0) || (kk > 0));
            }
            TCGEN05_COMMIT(sbase + 8);
        }

        if (j < 3) { prefetch_k(j+1); prefetch_v(j+1); }

        MBARRIER_WAIT_PARITY(sbase + 8, ps); ps ^= 1;
        TCGEN05_FENCE_AFTER();

        {
            char* Pb = smem + S_PT;
#pragma unroll
            for (int g = 0; g < 2; g++) {
                uint32_t r[32];
                TCGEN05_LD_32X32B_X32(r, tmem_S + half*64 + g*32);
                TCGEN05_WAIT_LD();
#pragma unroll
                for (int u = 0; u < 16; u++) {
                    float s0 = fminf(__uint_as_float(r[2*u]),   14.f);
                    float s1 = fminf(__uint_as_float(r[2*u+1]), 14.f);
                    uint32_t p2 = exp2_f16x2(s0, s1);
                    float2 f = __half22float2(*reinterpret_cast<__half2*>(&p2));
                    rsum += f.x + f.y;
                    int c = half*64 + g*32 + 2*u;
                    uint32_t boff = (uint32_t)(((row_g >> 3) + (c >> 6) * 16) * 1024 + (row_g & 7) * 128 + (c & 63) * 2);
                    *(uint32_t*)(Pb + SMEM_SWIZZLE_128B(boff)) = p2;
                }
            }
        }
        TCGEN05_FENCE_BEFORE();
        FENCE_PROXY_ASYNC();
        __syncthreads();

        if (wid == 0 && elect_one_pred()) {
            const uint64_t pd = MAKE_SMEM_DESC(sbase + S_PT);
            const uint64_t vd = MAKE_SMEM_DESC(sbase + S_VT);
#pragma unroll
            for (int ks = 0; ks < 8; ks++)
                mma_f16_ss(tmem_O,
                           pd + (uint64_t)(ks >> 2) * 1024 + (ks & 3) * 2,
                           vd + (uint64_t)(ks >> 2) * 512  + (ks & 3) * 2,
                           PV_IDESC, (j > 0) || (ks > 0));
            TCGEN05_COMMIT(sbase + 16);
        }
    }

    MBARRIER_WAIT_PARITY(sbase + 16, po);
    TCGEN05_FENCE_AFTER();

    float* red0 = (float*)(smem + S_RED0);
    float* red1 = (float*)(smem + S_RED1);
    if (half == 0) red0[row_g] = rsum; else red1[row_g] = rsum;
    __syncthreads();
    const float inv = 1.f / (red0[row_g] + red1[row_g]);

    uint32_t o[32];
    TCGEN05_LD_32X32B_X32(o, tmem_O + half * 32);
    TCGEN05_WAIT_LD();
    const int grow = b*SS + qt*128 + row_g;
#pragma unroll
    for (int u = 0; u < 8; u++) {
        float v0 = __uint_as_float(o[4*u+0]) * inv;
        float v1 = __uint_as_float(o[4*u+1]) * inv;
        float v2 = __uint_as_float(o[4*u+2]) * inv;
        float v3 = __uint_as_float(o[4*u+3]) * inv;
        __nv_bfloat16 h0,l0,h1,l1,h2,l2,h3,l3;
        split_one(v0,h0,l0); split_one(v1,h1,l1);
        split_one(v2,h2,l2); split_one(v3,h3,l3);
        const size_t oo = chunk_off((size_t)MM, grow, h*HDD + half*32 + u*4);
        *(uint2*)(ctx_hi + oo) = make_uint2(pack_bf2(h0,h1), pack_bf2(h2,h3));
        *(uint2*)(ctx_lo + oo) = make_uint2(pack_bf2(l0,l1), pack_bf2(l2,l3));
    }
    TCGEN05_FENCE_BEFORE();
    __syncthreads();
    if (tid == 0) { MBARRIER_INVAL(sbase + 8); MBARRIER_INVAL(sbase + 16); }
    if (wid == 0) TCGEN05_DEALLOC(tmem, 256);
#endif
}

// ---------------- residual + layernorm --------------------------------------
__device__ __forceinline__ float blockReduceSum(float val) {
    __shared__ float sm[32];
#pragma unroll
    for (int off = 16; off; off >>= 1) val += __shfl_xor_sync(0xffffffffu, val, off);
    __syncthreads();
    if ((threadIdx.x & 31) == 0) sm[threadIdx.x >> 5] = val;
    __syncthreads();
    if (threadIdx.x < 32) {
        float v = (threadIdx.x < (blockDim.x >> 5)) ? sm[threadIdx.x] : 0.f;
#pragma unroll
        for (int off = 16; off; off >>= 1) v += __shfl_xor_sync(0xffffffffu, v, off);
        if (threadIdx.x == 0) sm[0] = v;
    }
    __syncthreads();
    return sm[0];
}

__global__ __launch_bounds__(256)
void ln_kernel(const float* __restrict__ proj, const float* __restrict__ res,
               const float* __restrict__ gw, const float* __restrict__ bw,
               float* __restrict__ out) {
    int m = blockIdx.x, t = threadIdx.x;
    const float* p = proj + (size_t)m * HH;
    const float* r = res  + (size_t)m * HH;
    float x0 = p[t]     + r[t];
    float x1 = p[t+256] + r[t+256];
    float x2 = p[t+512] + r[t+512];
    float mu  = blockReduceSum(x0 + x1 + x2) * (1.f/HH);
    float d0 = x0 - mu, d1 = x1 - mu, d2 = x2 - mu;
    float var = blockReduceSum(d0*d0 + d1*d1 + d2*d2) * (1.f/HH);
    float inv = rsqrtf(var + 1e-12f);
    float* o = out + (size_t)m * HH;
    o[t]     = d0*inv*gw[t]     + bw[t];
    o[t+256] = d1*inv*gw[t+256] + bw[t+256];
    o[t+512] = d2*inv*gw[t+512] + bw[t+512];
}

// ---------------- launch ----------------------------------------------------
extern "C" void kernel_launch(void* const* d_in, const int* in_sizes, int n_in,
                              void* d_out, int out_size) {
    const float* hidden = (const float*)d_in[0];
    const float* colemb = (const float*)d_in[1];
    const int*   cat    = (const int*)  d_in[2];
    const int*   vmask  = (const int*)  d_in[3];
    const float* Wd = (const float*)d_in[4];  const float* bd = (const float*)d_in[5];
    const float* Wc = (const float*)d_in[6];  const float* bc = (const float*)d_in[7];
    const float* Wq = (const float*)d_in[8];  const float* bq = (const float*)d_in[9];
    const float* Wk = (const float*)d_in[10]; const float* bk = (const float*)d_in[11];
    const float* Wv = (const float*)d_in[12]; const float* bv = (const float*)d_in[13];
    const float* Wo = (const float*)d_in[14]; const float* bo = (const float*)d_in[15];
    const float* lng = (const float*)d_in[16]; const float* lnb = (const float*)d_in[17];
    float* out = (float*)d_out;

    __nv_bfloat16 *p_hid_hi, *p_hid_lo, *p_Wd_hi, *p_Wd_lo, *p_Wc_hi, *p_Wc_lo;
    __nv_bfloat16 *p_ce_hi, *p_ce_lo, *p_Wqkv_hi, *p_Wqkv_lo, *p_Wo_hi, *p_Wo_lo;
    __nv_bfloat16 *p_h_hi, *p_h_lo, *p_ctx_hi, *p_ctx_lo;
    float *p_colproj, *p_bcat, *p_zero, *p_bqkv, *p_h, *p_qkv, *p_proj;
    int *p_rowsrc;
    cudaGetSymbolAddress((void**)&p_hid_hi,  g_hid_hi);
    cudaGetSymbolAddress((void**)&p_hid_lo,  g_hid_lo);
    cudaGetSymbolAddress((void**)&p_Wd_hi,   g_Wd_hi);
    cudaGetSymbolAddress((void**)&p_Wd_lo,   g_Wd_lo);
    cudaGetSymbolAddress((void**)&p_Wc_hi,   g_Wc_hi);
    cudaGetSymbolAddress((void**)&p_Wc_lo,   g_Wc_lo);
    cudaGetSymbolAddress((void**)&p_ce_hi,   g_ce_hi);
    cudaGetSymbolAddress((void**)&p_ce_lo,   g_ce_lo);
    cudaGetSymbolAddress((void**)&p_colproj, g_colproj);
    cudaGetSymbolAddress((void**)&p_rowsrc,  g_rowsrc);
    cudaGetSymbolAddress((void**)&p_bcat,    g_bcat);
    cudaGetSymbolAddress((void**)&p_zero,    g_zero);
    cudaGetSymbolAddress((void**)&p_Wqkv_hi, g_Wqkv_hi);
    cudaGetSymbolAddress((void**)&p_Wqkv_lo, g_Wqkv_lo);
    cudaGetSymbolAddress((void**)&p_bqkv,    g_bqkv);
    cudaGetSymbolAddress((void**)&p_Wo_hi,   g_Wo_hi);
    cudaGetSymbolAddress((void**)&p_Wo_lo,   g_Wo_lo);
    cudaGetSymbolAddress((void**)&p_h,       g_h);
    cudaGetSymbolAddress((void**)&p_h_hi,    g_h_hi);
    cudaGetSymbolAddress((void**)&p_h_lo,    g_h_lo);
    cudaGetSymbolAddress((void**)&p_qkv,     g_qkv);
    cudaGetSymbolAddress((void**)&p_ctx_hi,  g_ctx_hi);
    cudaGetSymbolAddress((void**)&p_ctx_lo,  g_ctx_lo);
    cudaGetSymbolAddress((void**)&p_proj,    g_proj);

    cudaFuncSetAttribute(gemm_bf16x3, cudaFuncAttributeMaxDynamicSharedMemorySize, GEMM_SMEM_BYTES);
    cudaFuncSetAttribute(attn_tc, cudaFuncAttributeMaxDynamicSharedMemorySize, ATT_SMEM);

    // launch 0: merged prep (chunked layouts)
    prep_all<<<(NQKV*HH + 255)/256, 256>>>(Wd, bd, Wc, bc, Wq, bq, Wk, bk, Wv, bv,
                                           Wo, colemb, cat, vmask);
    // launch 1: split hidden (chunked)
    split_f32_ch<<<(MM*HH + 255)/256, 256>>>(hidden, p_hid_hi, p_hid_lo, MM, HH);

    // launch 2: colproj = masked(colemb) @ Wc^T
    gemm_bf16x3<<<dim3(HH/128, (BB*NCOLL)/128), 128, GEMM_SMEM_BYTES>>>(
        p_ce_hi, p_ce_lo, p_Wc_hi, p_Wc_lo, p_zero, p_colproj, nullptr, nullptr,
        BB*NCOLL, HH, HH, 0, nullptr, nullptr);

    // launch 3: h = gelu(hidden @ Wd^T + (bd+bc) + gather(colproj)); fused split
    gemm_bf16x3<<<dim3(HH/128, MM/128), 128, GEMM_SMEM_BYTES>>>(
        p_hid_hi, p_hid_lo, p_Wd_hi, p_Wd_lo, p_bcat, p_h, p_h_hi, p_h_lo,
        MM, HH, HH, 1, p_colproj, p_rowsrc);

    // launch 4: qkv = h @ Wqkv^T + bqkv
    gemm_bf16x3<<<dim3(NQKV/128, MM/128), 128, GEMM_SMEM_BYTES>>>(
        p_h_hi, p_h_lo, p_Wqkv_hi, p_Wqkv_lo, p_bqkv, p_qkv, nullptr, nullptr,
        MM, NQKV, HH, 0, nullptr, nullptr);

    // launch 5 (ncu capture slot): attention -> ctx hi/lo (chunked)
    attn_tc<<<dim3(SS/128, NHH, BB), 256, ATT_SMEM>>>(p_qkv, p_ctx_hi, p_ctx_lo);

    // launch 6: proj = ctx @ Wo^T + bo
    gemm_bf16x3<<<dim3(HH/128, MM/128), 128, GEMM_SMEM_BYTES>>>(
        p_ctx_hi, p_ctx_lo, p_Wo_hi, p_Wo_lo, bo, p_proj, nullptr, nullptr,
        MM, HH, HH, 0, nullptr, nullptr);

    // launch 7: out = LN(proj + h)
    ln_kernel<<<MM, 256>>>(p_proj, p_h, lng, lnb, out);
}